// round 11
// baseline (speedup 1.0000x reference)
#include <cuda_runtime.h>
#include <cuda_fp16.h>
#include <stdint.h>

// ============================================================================
// VideoContrastiveLoss on GB300 (sm_103 family target -> mma.sync HMMA path).
// Round 11: R10 (fp16-accum HMMA, upper-tri symmetry, 3 CTAs/SM) + fused
// rowloss/final-reduce kernel (last-block ticket, fixed-order sums ->
// deterministic), dropping one launch + ~5us of tail.
//   sim = normalize(f) @ normalize(f)^T / 0.07, diag=-inf, CE vs label i^4096.
// Fixed-shift softmax (logits <= 1/0.07 < 16), exact diagonal skip.
// ============================================================================

#define N_ROWS 8192
#define DIM    1024
#define TILE   128
#define NT64   64                    // 8192/128 tiles per side
#define N_CTAS (NT64 * (NT64 + 1) / 2)   // 2080 upper-tri tiles
#define KC     32
#define NKC    (DIM / KC)            // 32
#define STAGES 4
#define A_BYTES (TILE * 64)          // 128 rows x 32 fp16 (64B)
#define STAGE_BYTES (2 * A_BYTES)    // 16384
#define SMEM_K2 (STAGES * STAGE_BYTES)   // 65536 (x3 CTAs = 192KB <= 228KB)
#define INV_T  14.2857142857142857f
#define SHIFT  16.0f
#define LOSS_BLOCKS 64

__device__ __half g_fn[N_ROWS * DIM];            // normalized fp16 row-major
__device__ float g_rowpart[N_ROWS * NT64];       // tile (tr, g>=tr) row-side sums
__device__ float g_colpart[N_ROWS * NT64];       // tile (g<tr, tr) col-side sums
__device__ float g_pos[N_ROWS];
__device__ float g_rowloss[N_ROWS];
__device__ unsigned int g_ticket;                // reset by norm kernel each launch

// ---------------------------------------------------------------------------
__device__ __forceinline__ uint32_t smem_u32(const void* p) {
    uint32_t a;
    asm("{ .reg .u64 t; cvta.to.shared.u64 t, %1; cvt.u32.u64 %0, t; }"
        : "=r"(a) : "l"(p));
    return a;
}
__device__ __forceinline__ void cp16(uint32_t dst, const void* src) {
    asm volatile("cp.async.cg.shared.global [%0], [%1], 16;"
                 :: "r"(dst), "l"(src) : "memory");
}
__device__ __forceinline__ void cp_commit() {
    asm volatile("cp.async.commit_group;" ::: "memory");
}
template <int N> __device__ __forceinline__ void cp_wait() {
    asm volatile("cp.async.wait_group %0;" :: "n"(N) : "memory");
}
__device__ __forceinline__ void ldsm4(uint32_t& r0, uint32_t& r1, uint32_t& r2,
                                      uint32_t& r3, uint32_t addr) {
    asm volatile("ldmatrix.sync.aligned.m8n8.x4.shared.b16 {%0,%1,%2,%3}, [%4];"
                 : "=r"(r0), "=r"(r1), "=r"(r2), "=r"(r3) : "r"(addr));
}
// fp16 inputs, fp16 accumulators (2 packed f16x2 regs).
__device__ __forceinline__ void mma16816_f16(uint32_t& c0, uint32_t& c1,
                                             uint32_t a0, uint32_t a1, uint32_t a2,
                                             uint32_t a3, uint32_t b0, uint32_t b1) {
    asm volatile(
        "mma.sync.aligned.m16n8k16.row.col.f16.f16.f16.f16 "
        "{%0,%1}, {%2,%3,%4,%5}, {%6,%7}, {%0,%1};"
        : "+r"(c0), "+r"(c1)
        : "r"(a0), "r"(a1), "r"(a2), "r"(a3), "r"(b0), "r"(b1));
}
// XOR swizzle for 64B rows (4 x 16B quads): quad' = quad ^ ((row>>1)&3)
__device__ __forceinline__ uint32_t sw_off(int r, int q) {
    return (uint32_t)(r * 64 + ((q ^ ((r >> 1) & 3)) << 4));
}

// ============================================================================
// Kernel 1: row L2-normalize fp32 -> fp16 row-major. Also resets the ticket.
// ============================================================================
__global__ __launch_bounds__(256) void vcl_norm_kernel(const float* __restrict__ f) {
    if (blockIdx.x == 0 && threadIdx.x == 0) g_ticket = 0u;   // per-launch reset
    int row = blockIdx.x, tid = threadIdx.x;
    float4 x = reinterpret_cast<const float4*>(f)[row * (DIM / 4) + tid];
    float ss = x.x * x.x + x.y * x.y + x.z * x.z + x.w * x.w;
#pragma unroll
    for (int o = 16; o; o >>= 1) ss += __shfl_xor_sync(0xffffffffu, ss, o);
    __shared__ float red[8];
    if ((tid & 31) == 0) red[tid >> 5] = ss;
    __syncthreads();
    float tot = red[0] + red[1] + red[2] + red[3] + red[4] + red[5] + red[6] + red[7];
    float inv = 1.0f / fmaxf(sqrtf(tot), 1e-8f);
    __half2 lo = __floats2half2_rn(x.x * inv, x.y * inv);
    __half2 hi = __floats2half2_rn(x.z * inv, x.w * inv);
    uint2 v;
    v.x = reinterpret_cast<uint32_t&>(lo);
    v.y = reinterpret_cast<uint32_t&>(hi);
    reinterpret_cast<uint2*>(g_fn)[row * (DIM / 4) + tid] = v;
}

// ============================================================================
// Kernel 2: upper-tri tile (it<=jt): S[128x128] = A_it @ A_jt^T, fp16 accum,
// exp epilogue feeding row-side and col-side sums. 3 CTAs/SM.
// ============================================================================
__global__ __launch_bounds__(256, 3) void vcl_mma_kernel() {
    extern __shared__ char smem[];
    __shared__ float rowbuf[TILE];
    __shared__ float colbuf[TILE];
    const uint32_t sb = smem_u32(smem);
    const int tid = threadIdx.x;
    const int wid = tid >> 5, l = tid & 31;
    const int wm = wid >> 2, wn = wid & 3;   // warp grid 2x4, warp tile 64x32

    // decode linear upper-tri index -> (it, jt), it<=jt
    int it = 0, rem = blockIdx.x;
    while (rem >= NT64 - it) { rem -= NT64 - it; it++; }
    const int jt = it + rem;
    const bool isdiag = (it == jt);

    auto issue = [&](int kc, int stage) {
        uint32_t base = sb + (uint32_t)stage * STAGE_BYTES;
        const __half* gA = g_fn + (size_t)(it * TILE) * DIM + kc * KC;
        const __half* gB = g_fn + (size_t)(jt * TILE) * DIM + kc * KC;
#pragma unroll
        for (int i = 0; i < 2; i++) {            // A: 512 quads / 256 thr
            int idx = tid + i * 256;
            int r = idx >> 2, q = idx & 3;
            cp16(base + sw_off(r, q), gA + (size_t)r * DIM + q * 8);
        }
#pragma unroll
        for (int i = 0; i < 2; i++) {            // B: 512 quads
            int idx = tid + i * 256;
            int r = idx >> 2, q = idx & 3;
            cp16(base + A_BYTES + sw_off(r, q), gB + (size_t)r * DIM + q * 8);
        }
        cp_commit();
    };

    uint32_t acc[4][4][2];                       // f16x2 accumulators (zeroed)
#pragma unroll
    for (int a = 0; a < 4; a++)
#pragma unroll
        for (int b = 0; b < 4; b++) { acc[a][b][0] = 0u; acc[a][b][1] = 0u; }

    issue(0, 0); issue(1, 1); issue(2, 2);

    const int rA_in = (l & 7) + ((l >> 3) & 1) * 8;
    const int qA_hi = (l >> 4);
    const int rB_in = (l & 7) + ((l >> 4) ? 8 : 0);
    const int qB_hi = ((l >> 3) & 1);

    for (int kc = 0; kc < NKC; kc++) {
        cp_wait<STAGES - 2>();
        __syncthreads();
        if (kc + 3 < NKC) issue(kc + 3, (kc + 3) & (STAGES - 1));
        else cp_commit();

        uint32_t sA = sb + (uint32_t)(kc & (STAGES - 1)) * STAGE_BYTES;
        uint32_t sB = sA + A_BYTES;
#pragma unroll
        for (int kk = 0; kk < 2; kk++) {
            uint32_t af[4][4], bf2[2][4];
#pragma unroll
            for (int mt = 0; mt < 4; mt++) {
                int r = wm * 64 + mt * 16 + rA_in;
                ldsm4(af[mt][0], af[mt][1], af[mt][2], af[mt][3],
                      sA + sw_off(r, kk * 2 + qA_hi));
            }
#pragma unroll
            for (int np = 0; np < 2; np++) {
                int r = wn * 32 + np * 16 + rB_in;
                ldsm4(bf2[np][0], bf2[np][1], bf2[np][2], bf2[np][3],
                      sB + sw_off(r, kk * 2 + qB_hi));
            }
#pragma unroll
            for (int mt = 0; mt < 4; mt++)
#pragma unroll
                for (int nt = 0; nt < 4; nt++)
                    mma16816_f16(acc[mt][nt][0], acc[mt][nt][1],
                                 af[mt][0], af[mt][1], af[mt][2], af[mt][3],
                                 bf2[nt >> 1][(nt & 1) * 2],
                                 bf2[nt >> 1][(nt & 1) * 2 + 1]);
        }
    }
    cp_wait<0>();

    // ---- epilogue ----
    if (tid < TILE) rowbuf[tid] = 0.f;
    else colbuf[tid - TILE] = 0.f;
    __syncthreads();

    const int m0 = it * TILE + wm * 64;
    const int n0 = jt * TILE + wn * 32;
    const int lr = l >> 2;
    const int lc = 2 * (l & 3);
    float colacc[8];
#pragma unroll
    for (int i = 0; i < 8; i++) colacc[i] = 0.f;

#pragma unroll
    for (int mt = 0; mt < 4; mt++) {
#pragma unroll
        for (int h = 0; h < 2; h++) {
            int gr = m0 + mt * 16 + lr + h * 8;
            int lab = gr ^ (N_ROWS / 2);
            float s = 0.f;
#pragma unroll
            for (int nt = 0; nt < 4; nt++) {
                __half2 hv = *reinterpret_cast<__half2*>(&acc[mt][nt][h]);
                float2 vv = __half22float2(hv);   // .x = col lc, .y = col lc+1
#pragma unroll
                for (int cc = 0; cc < 2; cc++) {
                    int gc = n0 + nt * 8 + lc + cc;
                    float v = (cc == 0) ? vv.x : vv.y;
                    float e = __expf(fmaf(v, INV_T, -SHIFT));
                    if (gc == lab) {         // pair (gr,gc): capture both rows
                        float p = v * INV_T;
                        g_pos[gr] = p;
                        g_pos[gc] = p;       // never a diag tile (|gr-gc|=4096)
                    }
                    e = (gc == gr) ? 0.f : e;
                    s += e;
                    colacc[nt * 2 + cc] += e;
                }
            }
            // row reduce over the 4 lanes sharing this row
            s += __shfl_xor_sync(0xffffffffu, s, 1);
            s += __shfl_xor_sync(0xffffffffu, s, 2);
            if ((l & 3) == 0)
                atomicAdd(&rowbuf[wm * 64 + mt * 16 + lr + h * 8], s);
        }
    }
    if (!isdiag) {
        // col reduce: lanes {l, l^4, l^8, l^16} share the same 8 columns
#pragma unroll
        for (int i = 0; i < 8; i++) {
            float v = colacc[i];
            v += __shfl_xor_sync(0xffffffffu, v, 4);
            v += __shfl_xor_sync(0xffffffffu, v, 8);
            v += __shfl_xor_sync(0xffffffffu, v, 16);
            colacc[i] = v;
        }
        if (l < 4) {
#pragma unroll
            for (int nt = 0; nt < 4; nt++)
#pragma unroll
                for (int cc = 0; cc < 2; cc++)
                    atomicAdd(&colbuf[wn * 32 + nt * 8 + 2 * l + cc],
                              colacc[nt * 2 + cc]);
        }
    }
    __syncthreads();
    if (tid < TILE) {
        g_rowpart[(size_t)(it * TILE + tid) * NT64 + jt] = rowbuf[tid];
    } else if (!isdiag) {
        int c = tid - TILE;
        g_colpart[(size_t)(jt * TILE + c) * NT64 + it] = colbuf[c];
    }
}

// ============================================================================
// Kernel 3 (fused): per-row loss then, in the LAST block (ticket), the final
// fixed-order mean. No float atomics anywhere -> fully deterministic.
// ============================================================================
__global__ __launch_bounds__(256) void vcl_loss_kernel(float* __restrict__ out) {
    const int tid = threadIdx.x;
    const int wid = (blockIdx.x * 256 + tid) >> 5;   // 0..511
    const int l = tid & 31;

    for (int row = wid; row < N_ROWS; row += LOSS_BLOCKS * 8) {
        int tr = row >> 7;
        float s = 0.f;
#pragma unroll
        for (int g = l; g < NT64; g += 32)
            s += (g >= tr) ? g_rowpart[(size_t)row * NT64 + g]
                           : g_colpart[(size_t)row * NT64 + g];
#pragma unroll
        for (int o = 16; o; o >>= 1) s += __shfl_xor_sync(0xffffffffu, s, o);
        if (l == 0) g_rowloss[row] = (SHIFT + logf(s)) - g_pos[row];
    }

    // ---- last-block final reduction (fixed order -> deterministic) ----
    __shared__ bool is_last;
    __threadfence();                 // g_rowloss writes visible before ticket
    __syncthreads();
    if (tid == 0)
        is_last = (atomicAdd(&g_ticket, 1u) == LOSS_BLOCKS - 1u);
    __syncthreads();
    if (!is_last) return;

    float local = 0.f;
#pragma unroll
    for (int i = 0; i < N_ROWS / 256; i++)       // fixed order per thread
        local += g_rowloss[tid + i * 256];
#pragma unroll
    for (int o = 16; o; o >>= 1) local += __shfl_xor_sync(0xffffffffu, local, o);
    __shared__ float red[8];
    if (l == 0) red[tid >> 5] = local;
    __syncthreads();
    if (tid == 0) {
        float v = red[0] + red[1] + red[2] + red[3]
                + red[4] + red[5] + red[6] + red[7];
        out[0] = v * (1.0f / (float)N_ROWS);
    }
}

// ============================================================================
extern "C" void kernel_launch(void* const* d_in, const int* in_sizes, int n_in,
                              void* d_out, int out_size) {
    const float* feat = (const float*)d_in[0];
    float* out = (float*)d_out;

    cudaFuncSetAttribute(vcl_mma_kernel,
                         cudaFuncAttributeMaxDynamicSharedMemorySize, SMEM_K2);

    vcl_norm_kernel<<<N_ROWS, 256>>>(feat);
    vcl_mma_kernel<<<N_CTAS, 256, SMEM_K2>>>();
    vcl_loss_kernel<<<LOSS_BLOCKS, 256>>>(out);
}

// round 13
// speedup vs baseline: 1.0660x; 1.0660x over previous
#include <cuda_runtime.h>
#include <cuda_fp16.h>
#include <stdint.h>

// ============================================================================
// VideoContrastiveLoss on GB300 (sm_103 family target -> mma.sync HMMA path).
// Round 12: R11's fusion with CORRECT grids. R11 regressed because the fused
// loss kernel ran 512 warps (latency-bound tail needs ~2048 -> LOSS_BLOCKS
// 64->256). Also: warp-per-row norm (MLP=8/lane) to lift norm from 2.8 TB/s
// (12.1us) toward the 48MB streaming floor (~6-7us).
//   sim = normalize(f) @ normalize(f)^T / 0.07, diag=-inf, CE vs label i^4096.
// Upper-tri tiles; fp16-accum HMMA; fixed-shift softmax; exact diag skip.
// ============================================================================

#define N_ROWS 8192
#define DIM    1024
#define TILE   128
#define NT64   64                    // 8192/128 tiles per side
#define N_CTAS (NT64 * (NT64 + 1) / 2)   // 2080 upper-tri tiles
#define KC     32
#define NKC    (DIM / KC)            // 32
#define STAGES 4
#define A_BYTES (TILE * 64)          // 128 rows x 32 fp16 (64B)
#define STAGE_BYTES (2 * A_BYTES)    // 16384
#define SMEM_K2 (STAGES * STAGE_BYTES)   // 65536 (x3 CTAs = 192KB <= 228KB)
#define INV_T  14.2857142857142857f
#define SHIFT  16.0f
#define LOSS_BLOCKS 256              // 2048 warps: tail is latency-bound

__device__ __half g_fn[N_ROWS * DIM];            // normalized fp16 row-major
__device__ float g_rowpart[N_ROWS * NT64];       // tile (tr, g>=tr) row-side sums
__device__ float g_colpart[N_ROWS * NT64];       // tile (g<tr, tr) col-side sums
__device__ float g_pos[N_ROWS];
__device__ float g_rowloss[N_ROWS];
__device__ unsigned int g_ticket;                // reset by norm kernel each launch

// ---------------------------------------------------------------------------
__device__ __forceinline__ uint32_t smem_u32(const void* p) {
    uint32_t a;
    asm("{ .reg .u64 t; cvta.to.shared.u64 t, %1; cvt.u32.u64 %0, t; }"
        : "=r"(a) : "l"(p));
    return a;
}
__device__ __forceinline__ void cp16(uint32_t dst, const void* src) {
    asm volatile("cp.async.cg.shared.global [%0], [%1], 16;"
                 :: "r"(dst), "l"(src) : "memory");
}
__device__ __forceinline__ void cp_commit() {
    asm volatile("cp.async.commit_group;" ::: "memory");
}
template <int N> __device__ __forceinline__ void cp_wait() {
    asm volatile("cp.async.wait_group %0;" :: "n"(N) : "memory");
}
__device__ __forceinline__ void ldsm4(uint32_t& r0, uint32_t& r1, uint32_t& r2,
                                      uint32_t& r3, uint32_t addr) {
    asm volatile("ldmatrix.sync.aligned.m8n8.x4.shared.b16 {%0,%1,%2,%3}, [%4];"
                 : "=r"(r0), "=r"(r1), "=r"(r2), "=r"(r3) : "r"(addr));
}
// fp16 inputs, fp16 accumulators (2 packed f16x2 regs).
__device__ __forceinline__ void mma16816_f16(uint32_t& c0, uint32_t& c1,
                                             uint32_t a0, uint32_t a1, uint32_t a2,
                                             uint32_t a3, uint32_t b0, uint32_t b1) {
    asm volatile(
        "mma.sync.aligned.m16n8k16.row.col.f16.f16.f16.f16 "
        "{%0,%1}, {%2,%3,%4,%5}, {%6,%7}, {%0,%1};"
        : "+r"(c0), "+r"(c1)
        : "r"(a0), "r"(a1), "r"(a2), "r"(a3), "r"(b0), "r"(b1));
}
// XOR swizzle for 64B rows (4 x 16B quads): quad' = quad ^ ((row>>1)&3)
__device__ __forceinline__ uint32_t sw_off(int r, int q) {
    return (uint32_t)(r * 64 + ((q ^ ((r >> 1) & 3)) << 4));
}

// ============================================================================
// Kernel 1: row L2-normalize fp32 -> fp16, WARP per row (MLP=8 per lane).
// grid 1024 x 256 thr = 8192 warps. Also resets the ticket.
// ============================================================================
__global__ __launch_bounds__(256) void vcl_norm_kernel(const float* __restrict__ f) {
    if (blockIdx.x == 0 && threadIdx.x == 0) g_ticket = 0u;   // per-launch reset
    const int w = (blockIdx.x * 256 + threadIdx.x) >> 5;      // row 0..8191
    const int l = threadIdx.x & 31;
    const float4* r4 = reinterpret_cast<const float4*>(f) + (size_t)w * 256;

    float4 x[8];
    float ss = 0.f;
#pragma unroll
    for (int i = 0; i < 8; i++) {                 // front-batched: 8 loads in flight
        x[i] = r4[l + i * 32];
        ss = fmaf(x[i].x, x[i].x, fmaf(x[i].y, x[i].y,
             fmaf(x[i].z, x[i].z, fmaf(x[i].w, x[i].w, ss))));
    }
#pragma unroll
    for (int o = 16; o; o >>= 1) ss += __shfl_xor_sync(0xffffffffu, ss, o);
    float inv = 1.0f / fmaxf(sqrtf(ss), 1e-8f);

    uint2* dst = reinterpret_cast<uint2*>(g_fn) + (size_t)w * 256;
#pragma unroll
    for (int i = 0; i < 8; i++) {
        __half2 lo = __floats2half2_rn(x[i].x * inv, x[i].y * inv);
        __half2 hi = __floats2half2_rn(x[i].z * inv, x[i].w * inv);
        uint2 v;
        v.x = reinterpret_cast<uint32_t&>(lo);
        v.y = reinterpret_cast<uint32_t&>(hi);
        dst[l + i * 32] = v;
    }
}

// ============================================================================
// Kernel 2: upper-tri tile (it<=jt): S[128x128] = A_it @ A_jt^T, fp16 accum,
// exp epilogue feeding row-side and col-side sums. 3 CTAs/SM.
// ============================================================================
__global__ __launch_bounds__(256, 3) void vcl_mma_kernel() {
    extern __shared__ char smem[];
    __shared__ float rowbuf[TILE];
    __shared__ float colbuf[TILE];
    const uint32_t sb = smem_u32(smem);
    const int tid = threadIdx.x;
    const int wid = tid >> 5, l = tid & 31;
    const int wm = wid >> 2, wn = wid & 3;   // warp grid 2x4, warp tile 64x32

    // decode linear upper-tri index -> (it, jt), it<=jt
    int it = 0, rem = blockIdx.x;
    while (rem >= NT64 - it) { rem -= NT64 - it; it++; }
    const int jt = it + rem;
    const bool isdiag = (it == jt);

    auto issue = [&](int kc, int stage) {
        uint32_t base = sb + (uint32_t)stage * STAGE_BYTES;
        const __half* gA = g_fn + (size_t)(it * TILE) * DIM + kc * KC;
        const __half* gB = g_fn + (size_t)(jt * TILE) * DIM + kc * KC;
#pragma unroll
        for (int i = 0; i < 2; i++) {            // A: 512 quads / 256 thr
            int idx = tid + i * 256;
            int r = idx >> 2, q = idx & 3;
            cp16(base + sw_off(r, q), gA + (size_t)r * DIM + q * 8);
        }
#pragma unroll
        for (int i = 0; i < 2; i++) {            // B: 512 quads
            int idx = tid + i * 256;
            int r = idx >> 2, q = idx & 3;
            cp16(base + A_BYTES + sw_off(r, q), gB + (size_t)r * DIM + q * 8);
        }
        cp_commit();
    };

    uint32_t acc[4][4][2];                       // f16x2 accumulators (zeroed)
#pragma unroll
    for (int a = 0; a < 4; a++)
#pragma unroll
        for (int b = 0; b < 4; b++) { acc[a][b][0] = 0u; acc[a][b][1] = 0u; }

    issue(0, 0); issue(1, 1); issue(2, 2);

    const int rA_in = (l & 7) + ((l >> 3) & 1) * 8;
    const int qA_hi = (l >> 4);
    const int rB_in = (l & 7) + ((l >> 4) ? 8 : 0);
    const int qB_hi = ((l >> 3) & 1);

    for (int kc = 0; kc < NKC; kc++) {
        cp_wait<STAGES - 2>();
        __syncthreads();
        if (kc + 3 < NKC) issue(kc + 3, (kc + 3) & (STAGES - 1));
        else cp_commit();

        uint32_t sA = sb + (uint32_t)(kc & (STAGES - 1)) * STAGE_BYTES;
        uint32_t sB = sA + A_BYTES;
#pragma unroll
        for (int kk = 0; kk < 2; kk++) {
            uint32_t af[4][4], bf2[2][4];
#pragma unroll
            for (int mt = 0; mt < 4; mt++) {
                int r = wm * 64 + mt * 16 + rA_in;
                ldsm4(af[mt][0], af[mt][1], af[mt][2], af[mt][3],
                      sA + sw_off(r, kk * 2 + qA_hi));
            }
#pragma unroll
            for (int np = 0; np < 2; np++) {
                int r = wn * 32 + np * 16 + rB_in;
                ldsm4(bf2[np][0], bf2[np][1], bf2[np][2], bf2[np][3],
                      sB + sw_off(r, kk * 2 + qB_hi));
            }
#pragma unroll
            for (int mt = 0; mt < 4; mt++)
#pragma unroll
                for (int nt = 0; nt < 4; nt++)
                    mma16816_f16(acc[mt][nt][0], acc[mt][nt][1],
                                 af[mt][0], af[mt][1], af[mt][2], af[mt][3],
                                 bf2[nt >> 1][(nt & 1) * 2],
                                 bf2[nt >> 1][(nt & 1) * 2 + 1]);
        }
    }
    cp_wait<0>();

    // ---- epilogue ----
    if (tid < TILE) rowbuf[tid] = 0.f;
    else colbuf[tid - TILE] = 0.f;
    __syncthreads();

    const int m0 = it * TILE + wm * 64;
    const int n0 = jt * TILE + wn * 32;
    const int lr = l >> 2;
    const int lc = 2 * (l & 3);
    float colacc[8];
#pragma unroll
    for (int i = 0; i < 8; i++) colacc[i] = 0.f;

#pragma unroll
    for (int mt = 0; mt < 4; mt++) {
#pragma unroll
        for (int h = 0; h < 2; h++) {
            int gr = m0 + mt * 16 + lr + h * 8;
            int lab = gr ^ (N_ROWS / 2);
            float s = 0.f;
#pragma unroll
            for (int nt = 0; nt < 4; nt++) {
                __half2 hv = *reinterpret_cast<__half2*>(&acc[mt][nt][h]);
                float2 vv = __half22float2(hv);   // .x = col lc, .y = col lc+1
#pragma unroll
                for (int cc = 0; cc < 2; cc++) {
                    int gc = n0 + nt * 8 + lc + cc;
                    float v = (cc == 0) ? vv.x : vv.y;
                    float e = __expf(fmaf(v, INV_T, -SHIFT));
                    if (gc == lab) {         // pair (gr,gc): capture both rows
                        float p = v * INV_T;
                        g_pos[gr] = p;
                        g_pos[gc] = p;       // never a diag tile (|gr-gc|=4096)
                    }
                    e = (gc == gr) ? 0.f : e;
                    s += e;
                    colacc[nt * 2 + cc] += e;
                }
            }
            // row reduce over the 4 lanes sharing this row
            s += __shfl_xor_sync(0xffffffffu, s, 1);
            s += __shfl_xor_sync(0xffffffffu, s, 2);
            if ((l & 3) == 0)
                atomicAdd(&rowbuf[wm * 64 + mt * 16 + lr + h * 8], s);
        }
    }
    if (!isdiag) {
        // col reduce: lanes {l, l^4, l^8, l^16} share the same 8 columns
#pragma unroll
        for (int i = 0; i < 8; i++) {
            float v = colacc[i];
            v += __shfl_xor_sync(0xffffffffu, v, 4);
            v += __shfl_xor_sync(0xffffffffu, v, 8);
            v += __shfl_xor_sync(0xffffffffu, v, 16);
            colacc[i] = v;
        }
        if (l < 4) {
#pragma unroll
            for (int nt = 0; nt < 4; nt++)
#pragma unroll
                for (int cc = 0; cc < 2; cc++)
                    atomicAdd(&colbuf[wn * 32 + nt * 8 + 2 * l + cc],
                              colacc[nt * 2 + cc]);
        }
    }
    __syncthreads();
    if (tid < TILE) {
        g_rowpart[(size_t)(it * TILE + tid) * NT64 + jt] = rowbuf[tid];
    } else if (!isdiag) {
        int c = tid - TILE;
        g_colpart[(size_t)(jt * TILE + c) * NT64 + it] = colbuf[c];
    }
}

// ============================================================================
// Kernel 3 (fused): per-row loss (2048 warps) then, in the LAST block
// (ticket), the final fixed-order mean. No float atomics -> deterministic.
// ============================================================================
__global__ __launch_bounds__(256) void vcl_loss_kernel(float* __restrict__ out) {
    const int tid = threadIdx.x;
    const int wid = (blockIdx.x * 256 + tid) >> 5;   // 0..2047
    const int l = tid & 31;

    for (int row = wid; row < N_ROWS; row += LOSS_BLOCKS * 8) {
        int tr = row >> 7;
        float s = 0.f;
#pragma unroll
        for (int g = l; g < NT64; g += 32)
            s += (g >= tr) ? g_rowpart[(size_t)row * NT64 + g]
                           : g_colpart[(size_t)row * NT64 + g];
#pragma unroll
        for (int o = 16; o; o >>= 1) s += __shfl_xor_sync(0xffffffffu, s, o);
        if (l == 0) g_rowloss[row] = (SHIFT + logf(s)) - g_pos[row];
    }

    // ---- last-block final reduction (fixed order -> deterministic) ----
    __shared__ bool is_last;
    __threadfence();                 // g_rowloss writes visible before ticket
    __syncthreads();
    if (tid == 0)
        is_last = (atomicAdd(&g_ticket, 1u) == LOSS_BLOCKS - 1u);
    __syncthreads();
    if (!is_last) return;

    float local = 0.f;
#pragma unroll
    for (int i = 0; i < N_ROWS / 256; i++)       // fixed order per thread
        local += g_rowloss[tid + i * 256];
#pragma unroll
    for (int o = 16; o; o >>= 1) local += __shfl_xor_sync(0xffffffffu, local, o);
    __shared__ float red[8];
    if (l == 0) red[tid >> 5] = local;
    __syncthreads();
    if (tid == 0) {
        float v = red[0] + red[1] + red[2] + red[3]
                + red[4] + red[5] + red[6] + red[7];
        out[0] = v * (1.0f / (float)N_ROWS);
    }
}

// ============================================================================
extern "C" void kernel_launch(void* const* d_in, const int* in_sizes, int n_in,
                              void* d_out, int out_size) {
    const float* feat = (const float*)d_in[0];
    float* out = (float*)d_out;

    cudaFuncSetAttribute(vcl_mma_kernel,
                         cudaFuncAttributeMaxDynamicSharedMemorySize, SMEM_K2);

    vcl_norm_kernel<<<N_ROWS / 8, 256>>>(feat);
    vcl_mma_kernel<<<N_CTAS, 256, SMEM_K2>>>();
    vcl_loss_kernel<<<LOSS_BLOCKS, 256>>>(out);
}